// round 17
// baseline (speedup 1.0000x reference)
#include <cuda_runtime.h>
#include <cuda_fp16.h>
#include <cstdint>

#define B 512
#define HID 128
#define IN_DIM 595

#define TSTR 272            // B tile row stride (bytes) -> conflict-free ldmatrix
#define HJSTR 288           // permuted HJ row stride (8-bank offset/row -> conflict-free lds64)

// ---------------- device scratch (no allocations allowed) ----------------
__device__ float g_scratch[3 * B * HID];               // H2, U, V
__device__ __align__(16) unsigned char g_bsw[34816];   // C^T staged fp16

// ======================= helpers =======================
__device__ __forceinline__ uint32_t smem_u32(const void* p) {
    uint32_t a;
    asm("{ .reg .u64 t; cvta.to.shared.u64 t, %1; cvt.u32.u64 %0, t; }" : "=r"(a) : "l"(p));
    return a;
}
__device__ __forceinline__ void ldm4(uint32_t* r, uint32_t addr) {
    asm volatile("ldmatrix.sync.aligned.m8n8.x4.shared.b16 {%0,%1,%2,%3}, [%4];"
                 : "=r"(r[0]), "=r"(r[1]), "=r"(r[2]), "=r"(r[3]) : "r"(addr));
}
__device__ __forceinline__ void mma_fp16(float* c, const uint32_t* a, uint32_t b0, uint32_t b1) {
    asm volatile(
        "mma.sync.aligned.m16n8k16.row.col.f32.f16.f16.f32 "
        "{%0,%1,%2,%3}, {%4,%5,%6,%7}, {%8,%9}, {%0,%1,%2,%3};"
        : "+f"(c[0]), "+f"(c[1]), "+f"(c[2]), "+f"(c[3])
        : "r"(a[0]), "r"(a[1]), "r"(a[2]), "r"(a[3]), "r"(b0), "r"(b1));
}
__device__ __forceinline__ uint32_t habsdiff2(uint32_t a, uint32_t b) {
    __half2 r = __habs2(__hsub2(*(__half2*)&a, *(__half2*)&b));
    return *(uint32_t*)&r;
}
__device__ __forceinline__ uint2 lds64(uint32_t addr) {
    uint2 v;
    asm volatile("ld.shared.v2.b32 {%0,%1}, [%2];" : "=r"(v.x), "=r"(v.y) : "r"(addr));
    return v;
}

// ======================= fused encoder (whole chain) + prep =======================
__global__ __launch_bounds__(512) void enc_all(const float* __restrict__ x,
                                               const float* __restrict__ W1,
                                               const float* __restrict__ b1,
                                               const float* __restrict__ W2,
                                               const float* __restrict__ b2,
                                               const float* __restrict__ Wp1,
                                               const float* __restrict__ bp1,
                                               float* __restrict__ H2,
                                               float* __restrict__ U, float* __restrict__ V) {
    const int tid = threadIdx.x;
    const int bx = blockIdx.x;
    if (bx >= 256) {
        int idx = (bx - 256) * 512 + tid;           // < 16384
        int k = idx >> 7, d = idx & 127;
        float v = Wp1[(256 + d) * 128 + k];
        *(__half*)(g_bsw + (uint32_t)k * TSTR + d * 2) = __float2half_rn(v);
        return;
    }
    __shared__ float Xs[2 * 608];
    __shared__ float h1s[2][128], h2s[2][128];
    __shared__ float red[3][2][128];
    __shared__ float red2[2][256];
    const int m0 = bx * 2;
    const int n = tid & 127, q = tid >> 7;          // 4-way K split

    for (int idx = tid; idx < 2 * IN_DIM; idx += 512) {
        int r = idx < IN_DIM ? 0 : 1, k = idx < IN_DIM ? idx : idx - IN_DIM;
        Xs[r * 608 + k] = x[(size_t)(m0 + r) * IN_DIM + k];
    }
    __syncthreads();
    {
        const int kb = (IN_DIM * q) >> 2, ke = (IN_DIM * (q + 1)) >> 2;
        float a0 = 0.f, a1 = 0.f;
        const float* Wn = W1 + n;
#pragma unroll 8
        for (int k = kb; k < ke; ++k) {
            float w = __ldg(Wn + k * 128);
            a0 = fmaf(Xs[k], w, a0);
            a1 = fmaf(Xs[608 + k], w, a1);
        }
        if (q) { red[q - 1][0][n] = a0; red[q - 1][1][n] = a1; }
        __syncthreads();
        if (q == 0) {
            float bv = b1[n];
            h1s[0][n] = fmaxf(a0 + red[0][0][n] + red[1][0][n] + red[2][0][n] + bv, 0.f);
            h1s[1][n] = fmaxf(a1 + red[0][1][n] + red[1][1][n] + red[2][1][n] + bv, 0.f);
        }
        __syncthreads();
    }
    {
        float a0 = 0.f, a1 = 0.f;
        const float* Wn = W2 + n;
#pragma unroll 8
        for (int k = q * 32; k < q * 32 + 32; ++k) {
            float w = __ldg(Wn + k * 128);
            a0 = fmaf(h1s[0][k], w, a0);
            a1 = fmaf(h1s[1][k], w, a1);
        }
        if (q) { red[q - 1][0][n] = a0; red[q - 1][1][n] = a1; }
        __syncthreads();
        if (q == 0) {
            float bv = b2[n];
            float r0 = fmaxf(a0 + red[0][0][n] + red[1][0][n] + red[2][0][n] + bv, 0.f);
            float r1 = fmaxf(a1 + red[0][1][n] + red[1][1][n] + red[2][1][n] + bv, 0.f);
            h2s[0][n] = r0; h2s[1][n] = r1;
            H2[(size_t)m0 * 128 + n] = r0;
            H2[(size_t)(m0 + 1) * 128 + n] = r1;
        }
        __syncthreads();
    }
    {
        const int col = tid & 255, q2 = tid >> 8;
        const float* Wc = (col < 128) ? (Wp1 + col) : (Wp1 + 128 * 128 + (col - 128));
        float a0 = 0.f, a1 = 0.f;
#pragma unroll 8
        for (int k = q2 * 64; k < q2 * 64 + 64; ++k) {
            float w = __ldg(Wc + k * 128);
            a0 = fmaf(h2s[0][k], w, a0);
            a1 = fmaf(h2s[1][k], w, a1);
        }
        if (q2) { red2[0][col] = a0; red2[1][col] = a1; }
        __syncthreads();
        if (q2 == 0) {
            float bv = (col < 128) ? bp1[col] : 0.f;
            float r0 = a0 + red2[0][col] + bv;
            float r1 = a1 + red2[1][col] + bv;
            float* dst = (col < 128) ? U : V;
            int c = col & 127;
            dst[(size_t)m0 * 128 + c] = r0;
            dst[(size_t)(m0 + 1) * 128 + c] = r1;
        }
    }
}

// ======================= pairwise kernel: symmetric tiles, dual epilogue ============
// grid 160 (triangular tile set {p >= 16q}). M[i,j,:] = |h_i-h_j|C is symmetric, so
// each tile emits out[i,j] (U_i+V_j) AND out[j,i] (U_j+V_i) from the same acc.
#define OFF_B    0
#define OFF_HJP  34816       // 128 rows * 288 = 36864
#define OFF_HIS  71680       // 8 ii * 256 B
#define OFF_US   73728       // 8 * 512 B fp32
#define OFF_VS   77824       // 8 * 512 B fp32 (V of the i rows, for transposed epi)
#define OFF_W2   81920       // 512
#define OFF_RED  82432       // 2 buf * 2 var * 2 khalf * 128 * 4 = 4096
#define SMEM_PAIR 86528

__global__ __launch_bounds__(256, 2) void pair_mma(
    const float* __restrict__ H, const float* __restrict__ U, const float* __restrict__ V,
    const float* __restrict__ Wp2, const float* __restrict__ bp2, float* __restrict__ out) {
    extern __shared__ char sm[];
    const uint32_t sb = smem_u32(sm);
    float* w2  = (float*)(sm + OFF_W2);
    float* red = (float*)(sm + OFF_RED);   // [buf][var][khalf][128]

    const int tid  = threadIdx.x;
    const int lane = tid & 31, wid = tid >> 5;
    const int jg = wid & 3, khalf = wid >> 2;

    // triangular tile mapping: S = {(p,q): p >= 16q}
    int bx = blockIdx.x, p, q;
    if (bx < 64)       { q = 0; p = bx; }
    else if (bx < 112) { q = 1; p = bx - 64 + 16; }
    else if (bx < 144) { q = 2; p = bx - 112 + 32; }
    else               { q = 3; p = bx - 144 + 48; }
    const int i_base = p * 8;
    const int j0 = q * 128;

    // ---- stage B (C^T fp16, 34816 B = 2176 uint4) ----
    {
        const uint4* g = (const uint4*)g_bsw;
        uint4* s = (uint4*)(sm + OFF_B);
#pragma unroll
        for (int t = 0; t < 9; ++t) {
            int idx = tid + t * 256;
            if (idx < 2176) s[idx] = g[idx];
        }
    }
    const int j  = tid >> 1;
    const int dhalf = tid & 1;             // ks groups [dhalf*4, dhalf*4+4)

    // ---- stage HJP: quad-permuted fp16(h_j): [row][ks][qd] = {klo2, khi2} ----
    {
        const float4* Hj = (const float4*)(H + (size_t)(j0 + j) * HID + dhalf * 64);
        char* rowp = sm + OFF_HJP + (uint32_t)j * HJSTR;
#pragma unroll
        for (int g = 0; g < 4; ++g) {                 // ks = dhalf*4 + g
            const int ks = dhalf * 4 + g;
            float4 vlo = Hj[g * 4 + 0];
            float4 vlo2 = Hj[g * 4 + 1];
            float4 vhi = Hj[g * 4 + 2];
            float4 vhi2 = Hj[g * 4 + 3];
            __half2 l0 = __floats2half2_rn(vlo.x, vlo.y);
            __half2 l1 = __floats2half2_rn(vlo.z, vlo.w);
            __half2 l2 = __floats2half2_rn(vlo2.x, vlo2.y);
            __half2 l3 = __floats2half2_rn(vlo2.z, vlo2.w);
            __half2 h0 = __floats2half2_rn(vhi.x, vhi.y);
            __half2 h1 = __floats2half2_rn(vhi.z, vhi.w);
            __half2 h2 = __floats2half2_rn(vhi2.x, vhi2.y);
            __half2 h3 = __floats2half2_rn(vhi2.z, vhi2.w);
            uint32_t* w = (uint32_t*)(rowp + ks * 32);
            w[0] = *(uint32_t*)&l0; w[1] = *(uint32_t*)&h0;
            w[2] = *(uint32_t*)&l1; w[3] = *(uint32_t*)&h1;
            w[4] = *(uint32_t*)&l2; w[5] = *(uint32_t*)&h2;
            w[6] = *(uint32_t*)&l3; w[7] = *(uint32_t*)&h3;
        }
    }
    // ---- stage HIS (quad-permuted), Us, Vs; w2 ----
    if (tid < 128) {
        const int d = tid;
        const int ks = d >> 4, rem = d & 15;
        const int qd = (rem & 7) >> 1, half = rem >> 3, byt = rem & 1;
        const uint32_t off = ks * 32 + qd * 8 + half * 4 + byt * 2;
#pragma unroll
        for (int ii = 0; ii < 8; ++ii) {
            float hv = H[(size_t)(i_base + ii) * HID + d];
            *(__half*)(sm + OFF_HIS + ii * 256 + off) = __float2half_rn(hv);
            *(float*)(sm + OFF_US + ii * 512 + d * 4) = U[(size_t)(i_base + ii) * HID + d];
            *(float*)(sm + OFF_VS + ii * 512 + d * 4) = V[(size_t)(i_base + ii) * HID + d];
        }
        w2[tid] = Wp2[tid];
    }
    __syncthreads();

    const uint32_t bAddrBase = sb + OFF_B + (uint32_t)(khalf * 64 + (lane & 15)) * TSTR + (lane >> 4) * 16;
    const float b2v = bp2[0];
    const int rq  = lane >> 2;             // 0..7
    const int qd  = lane & 3;
    const int r0l = jg * 32 + rq;          // local rows r0l, +8, +16, +24
    const int kq  = qd * 2;
    const uint32_t hj0 = sb + OFF_HJP + (uint32_t)r0l * HJSTR + qd * 8;
    const uint32_t hj1 = hj0 + 8 * HJSTR;
    const uint32_t hj2 = hj0 + 16 * HJSTR;
    const uint32_t hj3 = hj0 + 24 * HJSTR;

    for (int ii = 0; ii < 8; ++ii) {
        const uint32_t hisB = sb + OFF_HIS + ii * 256 + qd * 8;

        float acc[2][8][4];
#pragma unroll
        for (int mt = 0; mt < 2; ++mt)
#pragma unroll
            for (int nt = 0; nt < 8; ++nt) {
                acc[mt][nt][0] = 0.f; acc[mt][nt][1] = 0.f;
                acc[mt][nt][2] = 0.f; acc[mt][nt][3] = 0.f;
            }
#pragma unroll
        for (int ks = 0; ks < 8; ++ks) {
            uint2 hi = lds64(hisB + ks * 32);
            uint2 a0 = lds64(hj0 + ks * 32);
            uint2 a1 = lds64(hj1 + ks * 32);
            uint2 a2 = lds64(hj2 + ks * 32);
            uint2 a3 = lds64(hj3 + ks * 32);
            uint32_t af0[4], af1[4];
            af0[0] = habsdiff2(a0.x, hi.x); af0[1] = habsdiff2(a1.x, hi.x);
            af0[2] = habsdiff2(a0.y, hi.y); af0[3] = habsdiff2(a1.y, hi.y);
            af1[0] = habsdiff2(a2.x, hi.x); af1[1] = habsdiff2(a3.x, hi.x);
            af1[2] = habsdiff2(a2.y, hi.y); af1[3] = habsdiff2(a3.y, hi.y);
            uint32_t bh[4][4];
#pragma unroll
            for (int p2 = 0; p2 < 4; ++p2)
                ldm4(bh[p2], bAddrBase + p2 * (16 * TSTR) + ks * 32);
#pragma unroll
            for (int nt = 0; nt < 8; ++nt) {
                uint32_t b0 = bh[nt >> 1][nt & 1], b1 = bh[nt >> 1][(nt & 1) + 2];
                mma_fp16(acc[0][nt], af0, b0, b1);
                mma_fp16(acc[1][nt], af1, b0, b1);
            }
        }

        const float* Usi = (const float*)(sm + OFF_US + ii * 512);
        const float* Vsi = (const float*)(sm + OFF_VS + ii * 512);
        float* rb = red + (ii & 1) * 512;

        // ---- epilogue pass 1 (direct): relu(M + U_i + V_j).w2 ----
        {
            float p0 = 0.f, p1 = 0.f, p2v = 0.f, p3 = 0.f;
#pragma unroll
            for (int nt = 0; nt < 8; ++nt) {
                const int k = khalf * 64 + nt * 8 + kq;
                float2 v0 = __ldg((const float2*)(V + (size_t)(j0 + r0l) * HID + k));
                float2 v1 = __ldg((const float2*)(V + (size_t)(j0 + r0l + 8) * HID + k));
                float2 v2 = __ldg((const float2*)(V + (size_t)(j0 + r0l + 16) * HID + k));
                float2 v3 = __ldg((const float2*)(V + (size_t)(j0 + r0l + 24) * HID + k));
                float u0 = Usi[k], u1 = Usi[k + 1];
                float w0 = w2[k], w1 = w2[k + 1];
                p0  = fmaf(fmaxf(acc[0][nt][0] + u0 + v0.x, 0.f), w0, p0);
                p0  = fmaf(fmaxf(acc[0][nt][1] + u1 + v0.y, 0.f), w1, p0);
                p1  = fmaf(fmaxf(acc[0][nt][2] + u0 + v1.x, 0.f), w0, p1);
                p1  = fmaf(fmaxf(acc[0][nt][3] + u1 + v1.y, 0.f), w1, p1);
                p2v = fmaf(fmaxf(acc[1][nt][0] + u0 + v2.x, 0.f), w0, p2v);
                p2v = fmaf(fmaxf(acc[1][nt][1] + u1 + v2.y, 0.f), w1, p2v);
                p3  = fmaf(fmaxf(acc[1][nt][2] + u0 + v3.x, 0.f), w0, p3);
                p3  = fmaf(fmaxf(acc[1][nt][3] + u1 + v3.y, 0.f), w1, p3);
            }
            p0  += __shfl_down_sync(0xffffffffu, p0, 2, 4);
            p0  += __shfl_down_sync(0xffffffffu, p0, 1, 4);
            p1  += __shfl_down_sync(0xffffffffu, p1, 2, 4);
            p1  += __shfl_down_sync(0xffffffffu, p1, 1, 4);
            p2v += __shfl_down_sync(0xffffffffu, p2v, 2, 4);
            p2v += __shfl_down_sync(0xffffffffu, p2v, 1, 4);
            p3  += __shfl_down_sync(0xffffffffu, p3, 2, 4);
            p3  += __shfl_down_sync(0xffffffffu, p3, 1, 4);
            if (qd == 0) {
                float* rd = rb + khalf * 128;
                rd[r0l]      = p0;
                rd[r0l + 8]  = p1;
                rd[r0l + 16] = p2v;
                rd[r0l + 24] = p3;
            }
        }
        // ---- epilogue pass 2 (transposed): relu(M + U_j + V_i).w2 ----
        {
            float p0 = 0.f, p1 = 0.f, p2v = 0.f, p3 = 0.f;
#pragma unroll
            for (int nt = 0; nt < 8; ++nt) {
                const int k = khalf * 64 + nt * 8 + kq;
                float2 u0j = __ldg((const float2*)(U + (size_t)(j0 + r0l) * HID + k));
                float2 u1j = __ldg((const float2*)(U + (size_t)(j0 + r0l + 8) * HID + k));
                float2 u2j = __ldg((const float2*)(U + (size_t)(j0 + r0l + 16) * HID + k));
                float2 u3j = __ldg((const float2*)(U + (size_t)(j0 + r0l + 24) * HID + k));
                float vv0 = Vsi[k], vv1 = Vsi[k + 1];
                float w0 = w2[k], w1 = w2[k + 1];
                p0  = fmaf(fmaxf(acc[0][nt][0] + u0j.x + vv0, 0.f), w0, p0);
                p0  = fmaf(fmaxf(acc[0][nt][1] + u0j.y + vv1, 0.f), w1, p0);
                p1  = fmaf(fmaxf(acc[0][nt][2] + u1j.x + vv0, 0.f), w0, p1);
                p1  = fmaf(fmaxf(acc[0][nt][3] + u1j.y + vv1, 0.f), w1, p1);
                p2v = fmaf(fmaxf(acc[1][nt][0] + u2j.x + vv0, 0.f), w0, p2v);
                p2v = fmaf(fmaxf(acc[1][nt][1] + u2j.y + vv1, 0.f), w1, p2v);
                p3  = fmaf(fmaxf(acc[1][nt][2] + u3j.x + vv0, 0.f), w0, p3);
                p3  = fmaf(fmaxf(acc[1][nt][3] + u3j.y + vv1, 0.f), w1, p3);
            }
            p0  += __shfl_down_sync(0xffffffffu, p0, 2, 4);
            p0  += __shfl_down_sync(0xffffffffu, p0, 1, 4);
            p1  += __shfl_down_sync(0xffffffffu, p1, 2, 4);
            p1  += __shfl_down_sync(0xffffffffu, p1, 1, 4);
            p2v += __shfl_down_sync(0xffffffffu, p2v, 2, 4);
            p2v += __shfl_down_sync(0xffffffffu, p2v, 1, 4);
            p3  += __shfl_down_sync(0xffffffffu, p3, 2, 4);
            p3  += __shfl_down_sync(0xffffffffu, p3, 1, 4);
            if (qd == 0) {
                float* rt = rb + 256 + khalf * 128;
                rt[r0l]      = p0;
                rt[r0l + 8]  = p1;
                rt[r0l + 16] = p2v;
                rt[r0l + 24] = p3;
            }
        }
        __syncthreads();
        if (tid < 128) {
            const float* rbuf = red + (ii & 1) * 512;
            out[(size_t)(i_base + ii) * B + j0 + tid] = rbuf[tid] + rbuf[128 + tid] + b2v;
            out[(size_t)(j0 + tid) * B + i_base + ii] = rbuf[256 + tid] + rbuf[384 + tid] + b2v;
        }
    }
}

// ======================= launch =======================
extern "C" void kernel_launch(void* const* d_in, const int* in_sizes, int n_in,
                              void* d_out, int out_size) {
    const float* x   = (const float*)d_in[0];
    const float* W1  = (const float*)d_in[1];
    const float* b1  = (const float*)d_in[2];
    const float* W2  = (const float*)d_in[3];
    const float* b2  = (const float*)d_in[4];
    const float* Wp1 = (const float*)d_in[5];
    const float* bp1 = (const float*)d_in[6];
    const float* Wp2 = (const float*)d_in[7];
    const float* bp2 = (const float*)d_in[8];
    float* out = (float*)d_out;

    float* sp = nullptr;
    cudaGetSymbolAddress((void**)&sp, g_scratch);
    float* H2 = sp;
    float* U  = sp + B * HID;
    float* V  = sp + 2 * B * HID;

    enc_all<<<288, 512>>>(x, W1, b1, W2, b2, Wp1, bp1, H2, U, V);

    cudaFuncSetAttribute(pair_mma, cudaFuncAttributeMaxDynamicSharedMemorySize, SMEM_PAIR);
    pair_mma<<<160, 256, SMEM_PAIR>>>(H2, U, V, Wp2, bp2, out);
}